// round 10
// baseline (speedup 1.0000x reference)
#include <cuda_runtime.h>
#include <cuda_bf16.h>
#include <cstdint>

// Problem constants (fixed by the reference).
#define N_ENT   50000
#define N_REL   16
#define N_BASES 8
#define H_DIM   128
#define N_EDGES 800000

// ---------------------------------------------------------------------------
// Device scratch (allocation-free rule: __device__ globals).
// ---------------------------------------------------------------------------
__device__ __nv_bfloat16 g_Wt_hi[17 * H_DIM * H_DIM];   // [r][o][i]  (N,K) K-major
__device__ __nv_bfloat16 g_Wt_lo[17 * H_DIM * H_DIM];
__device__ __nv_bfloat16 g_A_hi[(size_t)N_ENT * H_DIM];
__device__ __nv_bfloat16 g_A_lo[(size_t)N_ENT * H_DIM];
__device__ float         g_HR[(size_t)N_REL * N_ENT * H_DIM];
__device__ float         g_H1[(size_t)N_ENT * H_DIM];
__device__ int           g_cnt[N_ENT];
__device__ int           g_off[N_ENT];
__device__ int           g_cur[N_ENT];
__device__ uint32_t      g_pay[N_EDGES];   // rel*N_ENT + src, grouped by dst

// ---------------------------------------------------------------------------
// helpers
// ---------------------------------------------------------------------------
__device__ __forceinline__ uint32_t smem_u32(const void* p) {
    uint32_t a;
    asm("{ .reg .u64 t; cvta.to.shared.u64 t, %1; cvt.u32.u64 %0, t; }"
        : "=r"(a) : "l"(p));
    return a;
}

#define LDMX4(r0, r1, r2, r3, addr)                                           \
    asm volatile("ldmatrix.sync.aligned.m8n8.x4.shared.b16 {%0,%1,%2,%3}, [%4];" \
                 : "=r"(r0), "=r"(r1), "=r"(r2), "=r"(r3) : "r"(addr))

#define MMA_BF16(C, A, B)                                                     \
    asm volatile(                                                             \
        "mma.sync.aligned.m16n8k16.row.col.f32.bf16.bf16.f32 "                \
        "{%0,%1,%2,%3}, {%4,%5,%6,%7}, {%8,%9}, {%0,%1,%2,%3};"               \
        : "+f"((C)[0]), "+f"((C)[1]), "+f"((C)[2]), "+f"((C)[3])              \
        : "r"((A)[0]), "r"((A)[1]), "r"((A)[2]), "r"((A)[3]),                 \
          "r"((B)[0]), "r"((B)[1]))

#define CP_ASYNC16(dst, src)                                                  \
    asm volatile("cp.async.cg.shared.global [%0], [%1], 16;"                  \
                 :: "r"(dst), "l"(src))
#define CP_COMMIT()  asm volatile("cp.async.commit_group;" ::: "memory")
#define CP_WAIT0()   asm volatile("cp.async.wait_group 0;" ::: "memory")

// ---------------------------------------------------------------------------
// Edge binning by dst (proven).
// ---------------------------------------------------------------------------
__global__ void zero_cnt_kernel(int* __restrict__ cnt)
{
    int i = blockIdx.x * blockDim.x + threadIdx.x;
    if (i < N_ENT) cnt[i] = 0;
}

__global__ void hist_kernel(const int* __restrict__ dst,
                            int* __restrict__ cnt, int E)
{
    int e = blockIdx.x * blockDim.x + threadIdx.x;
    if (e >= E) return;
    atomicAdd(&cnt[dst[e]], 1);
}

__global__ __launch_bounds__(1024)
void scan_kernel(const int* __restrict__ cnt,
                 int* __restrict__ off, int* __restrict__ cur)
{
    __shared__ int ps[1024];
    const int t = threadIdx.x;
    const int CH = (N_ENT + 1023) / 1024;
    const int lo = t * CH;
    const int hi = min(lo + CH, N_ENT);
    int s = 0;
    for (int i = lo; i < hi; i++) s += cnt[i];
    ps[t] = s;
    __syncthreads();
    for (int d = 1; d < 1024; d <<= 1) {
        int v = (t >= d) ? ps[t - d] : 0;
        __syncthreads();
        ps[t] += v;
        __syncthreads();
    }
    int run = ps[t] - s;
    for (int i = lo; i < hi; i++) {
        off[i] = run;
        cur[i] = run;
        run += cnt[i];
    }
}

__global__ void fill_kernel(const int* __restrict__ src,
                            const int* __restrict__ dst,
                            const int* __restrict__ rel,
                            int* __restrict__ cur,
                            uint32_t* __restrict__ pay, int E)
{
    int e = blockIdx.x * blockDim.x + threadIdx.x;
    if (e >= E) return;
    int pos = atomicAdd(&cur[dst[e]], 1);
    pay[pos] = (uint32_t)(rel[e] * N_ENT + src[e]);
}

// ---------------------------------------------------------------------------
// Combine bases -> transposed bf16 hi/lo weights.
// ---------------------------------------------------------------------------
__global__ void combine_bases_kernel(const float* __restrict__ basis,
                                     const float* __restrict__ w_comp,
                                     const float* __restrict__ loop_w,
                                     __nv_bfloat16* __restrict__ Wt_hi,
                                     __nv_bfloat16* __restrict__ Wt_lo)
{
    int idx = blockIdx.x * blockDim.x + threadIdx.x;
    const int total = 17 * H_DIM * H_DIM;
    if (idx >= total) return;
    int r  = idx >> 14;
    int io = idx & 16383;          // i*128 + o
    float s;
    if (r < N_REL) {
        s = 0.f;
#pragma unroll
        for (int b = 0; b < N_BASES; b++)
            s += w_comp[r * N_BASES + b] * basis[b * (H_DIM * H_DIM) + io];
    } else {
        s = loop_w[io];
    }
    int i = io >> 7, o = io & 127;
    size_t oidx = (size_t)r * 16384 + o * 128 + i;   // [r][o][i]
    __nv_bfloat16 hi = __float2bfloat16(s);
    __nv_bfloat16 lo = __float2bfloat16(s - __bfloat162float(hi));
    Wt_hi[oidx] = hi;
    Wt_lo[oidx] = lo;
}

// ---------------------------------------------------------------------------
// Split input activations fp32 -> bf16 hi/lo (optional fused ReLU).
// ---------------------------------------------------------------------------
__global__ void split_kernel(const float* __restrict__ x,
                             __nv_bfloat16* __restrict__ hi,
                             __nv_bfloat16* __restrict__ lo,
                             int n4, int relu)
{
    int i = blockIdx.x * blockDim.x + threadIdx.x;
    if (i >= n4) return;
    float4 v = ((const float4*)x)[i];
    if (relu) {
        v.x = fmaxf(v.x, 0.f); v.y = fmaxf(v.y, 0.f);
        v.z = fmaxf(v.z, 0.f); v.w = fmaxf(v.w, 0.f);
    }
    float e[4] = {v.x, v.y, v.z, v.w};
    __nv_bfloat16 h[4], l[4];
#pragma unroll
    for (int j = 0; j < 4; j++) {
        h[j] = __float2bfloat16(e[j]);
        l[j] = __float2bfloat16(e[j] - __bfloat162float(h[j]));
    }
    ((__nv_bfloat162*)hi)[2 * i]     = __nv_bfloat162(h[0], h[1]);
    ((__nv_bfloat162*)hi)[2 * i + 1] = __nv_bfloat162(h[2], h[3]);
    ((__nv_bfloat162*)lo)[2 * i]     = __nv_bfloat162(l[0], l[1]);
    ((__nv_bfloat162*)lo)[2 * i + 1] = __nv_bfloat162(l[2], l[3]);
}

// ---------------------------------------------------------------------------
// bf16 mma.sync GEMM, CTA tile 128x128, 4 warps of 64x64 (2x2), A resident
// across all 17 r's, W double-buffered via cp.async, 3-term bf16 split.
// Fragments amortized 2x better: 16 LDMX4 / 96 MMA per warp-kstep ->
// smem crossbar (old limiter) drops below tensor-pipe demand.
// r<16 -> HR[r]; r==16 -> OUT (+bias).
// ---------------------------------------------------------------------------
#define PITCH    272                    // 256B row + 16B pad
#define SM_A_HI  0
#define SM_A_LO  34816                  // 128*272
#define SM_W0    69632                  // W stage 0: hi @+0, lo @+34816
#define W_STAGE  69632                  // bytes per stage (hi+lo)
#define GEMM_SMEM (SM_W0 + 2 * W_STAGE) // 208896

__global__ __launch_bounds__(128, 1)
void gemm_bf16_kernel(const __nv_bfloat16* __restrict__ Ahi,
                      const __nv_bfloat16* __restrict__ Alo,
                      const __nv_bfloat16* __restrict__ Wthi,
                      const __nv_bfloat16* __restrict__ Wtlo,
                      const float* __restrict__ bias,
                      float* __restrict__ HR,
                      float* __restrict__ OUT,
                      int M)
{
    extern __shared__ char smem[];
    const uint32_t sb = smem_u32(smem);
    const int tid   = threadIdx.x;
    const int wid   = tid >> 5;              // 0..3
    const int lane  = tid & 31;
    const int wm    = wid >> 1;              // 0..1  (64-row strips)
    const int wn    = wid & 1;               // 0..1  (64-col strips)
    const int m0    = blockIdx.x * 128;

    // ---- A tiles (hi, lo) via cp.async; OOB rows zeroed by STS ----
#pragma unroll
    for (int t = 0; t < 2; t++) {
        const __nv_bfloat16* src = t ? Alo : Ahi;
        const uint32_t base = sb + (t ? SM_A_LO : SM_A_HI);
#pragma unroll
        for (int i = 0; i < 16; i++) {
            int idx = tid + i * 128;         // 0..2047
            int row = idx >> 4;
            int c   = idx & 15;
            uint32_t dst = base + row * PITCH + c * 16;
            if (m0 + row < M)
                CP_ASYNC16(dst, src + (size_t)(m0 + row) * H_DIM + c * 8);
            else
                *(uint4*)(smem + (dst - sb)) = make_uint4(0u, 0u, 0u, 0u);
        }
    }
    // ---- prefetch W[0] into stage 0 ----
#pragma unroll
    for (int t = 0; t < 2; t++) {
        const __nv_bfloat16* src = t ? Wtlo : Wthi;
        const uint32_t base = sb + SM_W0 + t * 34816;
#pragma unroll
        for (int i = 0; i < 16; i++) {
            int idx = tid + i * 128;
            int row = idx >> 4;
            int c   = idx & 15;
            CP_ASYNC16(base + row * PITCH + c * 16,
                       src + (size_t)row * H_DIM + c * 8);
        }
    }
    CP_COMMIT();

    // ldmatrix per-lane address components
    const int q   = lane >> 3;               // 0..3
    const int r8  = lane & 7;
    const int arow_base = wm * 64 + r8 + (q & 1) * 8;     // + mt*16
    const int acol_add  = (q >> 1) * 8;                   // + k0
    const int brow_base = wn * 64 + (q >> 1) * 8 + r8;    // + p*16
    const int bcol_add  = (q & 1) * 8;                    // + k0
    const int gr0 = m0 + wm * 64 + (lane >> 2);

    for (int r = 0; r < 17; r++) {
        CP_WAIT0();
        __syncthreads();                 // W[r] visible; other stage free

        // prefetch W[r+1] into the other stage (overlaps MMA + epilogue)
        if (r < 16) {
            const uint32_t sbase = sb + SM_W0 + ((r + 1) & 1) * W_STAGE;
#pragma unroll
            for (int t = 0; t < 2; t++) {
                const __nv_bfloat16* src =
                    (t ? Wtlo : Wthi) + (size_t)(r + 1) * 16384;
                const uint32_t base = sbase + t * 34816;
#pragma unroll
                for (int i = 0; i < 16; i++) {
                    int idx = tid + i * 128;
                    int row = idx >> 4;
                    int c   = idx & 15;
                    CP_ASYNC16(base + row * PITCH + c * 16,
                               src + (size_t)row * H_DIM + c * 8);
                }
            }
            CP_COMMIT();
        }

        const uint32_t wb = sb + SM_W0 + (r & 1) * W_STAGE;   // hi; lo @+34816

        float acc[4][8][4];
#pragma unroll
        for (int mt = 0; mt < 4; mt++)
#pragma unroll
            for (int nt = 0; nt < 8; nt++)
#pragma unroll
                for (int c = 0; c < 4; c++) acc[mt][nt][c] = 0.f;

#pragma unroll
        for (int ks = 0; ks < 8; ks++) {
            const int k0 = ks * 16;
            uint32_t ah[4][4], al[4][4], bh[8][2], bl[8][2];
#pragma unroll
            for (int mt = 0; mt < 4; mt++) {
                uint32_t off = (uint32_t)((arow_base + mt * 16) * PITCH
                                          + (k0 + acol_add) * 2);
                LDMX4(ah[mt][0], ah[mt][1], ah[mt][2], ah[mt][3], sb + SM_A_HI + off);
                LDMX4(al[mt][0], al[mt][1], al[mt][2], al[mt][3], sb + SM_A_LO + off);
            }
#pragma unroll
            for (int p = 0; p < 4; p++) {
                uint32_t off = (uint32_t)((brow_base + p * 16) * PITCH
                                          + (k0 + bcol_add) * 2);
                LDMX4(bh[2 * p][0], bh[2 * p][1], bh[2 * p + 1][0], bh[2 * p + 1][1],
                      wb + off);
                LDMX4(bl[2 * p][0], bl[2 * p][1], bl[2 * p + 1][0], bl[2 * p + 1][1],
                      wb + 34816 + off);
            }
#pragma unroll
            for (int mt = 0; mt < 4; mt++)
#pragma unroll
                for (int nt = 0; nt < 8; nt++) {
                    MMA_BF16(acc[mt][nt], ah[mt], bh[nt]);
                    MMA_BF16(acc[mt][nt], ah[mt], bl[nt]);
                    MMA_BF16(acc[mt][nt], al[mt], bh[nt]);
                }
        }

        // ---- epilogue (registers -> global) ----
        float* base = (r < N_REL) ? (HR + (size_t)r * N_ENT * H_DIM) : OUT;
#pragma unroll
        for (int mt = 0; mt < 4; mt++) {
            int row = gr0 + mt * 16;
#pragma unroll
            for (int nt = 0; nt < 8; nt++) {
                int col = wn * 64 + nt * 8 + (lane & 3) * 2;
                float b0 = 0.f, b1 = 0.f;
                if (r == N_REL) {
                    float2 bv = *(const float2*)(bias + col);
                    b0 = bv.x; b1 = bv.y;
                }
                if (row < M)
                    *(float2*)(base + (size_t)row * H_DIM + col) =
                        make_float2(acc[mt][nt][0] + b0, acc[mt][nt][1] + b1);
                if (row + 8 < M)
                    *(float2*)(base + (size_t)(row + 8) * H_DIM + col) =
                        make_float2(acc[mt][nt][2] + b0, acc[mt][nt][3] + b1);
            }
        }
    }
}

// ---------------------------------------------------------------------------
// CSR-by-dst scatter, NO atomics (proven).
// ---------------------------------------------------------------------------
__global__ void scatter_csr_kernel(const float* __restrict__ HR,
                                   const int* __restrict__ off,
                                   const int* __restrict__ cnt,
                                   const uint32_t* __restrict__ pay,
                                   float* __restrict__ out)
{
    int w    = (blockIdx.x * blockDim.x + threadIdx.x) >> 5;
    int lane = threadIdx.x & 31;
    if (w >= N_ENT) return;
    int n = cnt[w];
    if (n == 0) return;
    int o = off[w];

    float4 acc = make_float4(0.f, 0.f, 0.f, 0.f);
    for (int e = 0; e < n; e++) {
        uint32_t gi = pay[o + e];
        const float4 v = *(const float4*)(HR + (size_t)gi * H_DIM + lane * 4);
        acc.x += v.x; acc.y += v.y; acc.z += v.z; acc.w += v.w;
    }
    float* op = out + (size_t)w * H_DIM + lane * 4;
    float4 c = *(const float4*)op;
    c.x += acc.x; c.y += acc.y; c.z += acc.z; c.w += acc.w;
    *(float4*)op = c;
}

// ---------------------------------------------------------------------------
// Final ReLU.
// ---------------------------------------------------------------------------
__global__ void relu_kernel(float* __restrict__ x, int n4)
{
    int i = blockIdx.x * blockDim.x + threadIdx.x;
    if (i >= n4) return;
    float4 v = ((float4*)x)[i];
    v.x = fmaxf(v.x, 0.f); v.y = fmaxf(v.y, 0.f);
    v.z = fmaxf(v.z, 0.f); v.w = fmaxf(v.w, 0.f);
    ((float4*)x)[i] = v;
}

// ---------------------------------------------------------------------------
// Launch. Order keeps gemm (layer 1) in the ncu-profiled slot (#4).
// ---------------------------------------------------------------------------
extern "C" void kernel_launch(void* const* d_in, const int* in_sizes, int n_in,
                              void* d_out, int out_size)
{
    const float* entity_emb = (const float*)d_in[0];
    const float* basis1     = (const float*)d_in[1];
    const float* w_comp1    = (const float*)d_in[2];
    const float* loop_w1    = (const float*)d_in[3];
    const float* bias1      = (const float*)d_in[4];
    const float* basis2     = (const float*)d_in[5];
    const float* w_comp2    = (const float*)d_in[6];
    const float* loop_w2    = (const float*)d_in[7];
    const float* bias2      = (const float*)d_in[8];
    const int*   src        = (const int*)d_in[9];
    const int*   dst        = (const int*)d_in[10];
    const int*   rel        = (const int*)d_in[11];
    float*       out        = (float*)d_out;

    const int E = in_sizes[9];

    __nv_bfloat16 *dWth, *dWtl, *dAh, *dAl;
    float *dHR, *dH1;
    int *dcnt, *doff, *dcur;
    uint32_t *dpay;
    cudaGetSymbolAddress((void**)&dWth, g_Wt_hi);
    cudaGetSymbolAddress((void**)&dWtl, g_Wt_lo);
    cudaGetSymbolAddress((void**)&dAh,  g_A_hi);
    cudaGetSymbolAddress((void**)&dAl,  g_A_lo);
    cudaGetSymbolAddress((void**)&dHR,  g_HR);
    cudaGetSymbolAddress((void**)&dH1,  g_H1);
    cudaGetSymbolAddress((void**)&dcnt, g_cnt);
    cudaGetSymbolAddress((void**)&doff, g_off);
    cudaGetSymbolAddress((void**)&dcur, g_cur);
    cudaGetSymbolAddress((void**)&dpay, g_pay);

    cudaFuncSetAttribute(gemm_bf16_kernel,
                         cudaFuncAttributeMaxDynamicSharedMemorySize, GEMM_SMEM);

    const int cb_blocks = (17 * H_DIM * H_DIM + 255) / 256;
    const int n4        = N_ENT * H_DIM / 4;
    const int sp_blocks = (n4 + 255) / 256;
    const int eg_blocks = (E + 255) / 256;
    const int zc_blocks = (N_ENT + 255) / 256;
    const int gemm_grid = (N_ENT + 127) / 128;       // 391
    const int csr_blocks = (N_ENT * 32 + 255) / 256;

    // #1..#4 (gemm layer-1 lands in the profiled slot)
    combine_bases_kernel<<<cb_blocks, 256>>>(basis1, w_comp1, loop_w1, dWth, dWtl);
    split_kernel<<<sp_blocks, 256>>>(entity_emb, dAh, dAl, n4, 0);
    zero_cnt_kernel<<<zc_blocks, 256>>>(dcnt);
    gemm_bf16_kernel<<<gemm_grid, 128, GEMM_SMEM>>>(dAh, dAl, dWth, dWtl, bias1,
                                                    dHR, dH1, N_ENT);
    // binning (needed before scatter)
    hist_kernel<<<eg_blocks, 256>>>(dst, dcnt, E);
    scan_kernel<<<1, 1024>>>(dcnt, doff, dcur);
    fill_kernel<<<eg_blocks, 256>>>(src, dst, rel, dcur, dpay, E);
    scatter_csr_kernel<<<csr_blocks, 256>>>(dHR, doff, dcnt, dpay, dH1);

    // ---------------- Layer 2 ----------------
    combine_bases_kernel<<<cb_blocks, 256>>>(basis2, w_comp2, loop_w2, dWth, dWtl);
    split_kernel<<<sp_blocks, 256>>>(dH1, dAh, dAl, n4, 1);   // fused ReLU
    gemm_bf16_kernel<<<gemm_grid, 128, GEMM_SMEM>>>(dAh, dAl, dWth, dWtl, bias2,
                                                    dHR, out, N_ENT);
    scatter_csr_kernel<<<csr_blocks, 256>>>(dHR, doff, dcnt, dpay, out);
    relu_kernel<<<sp_blocks, 256>>>(out, n4);
}

// round 11
// speedup vs baseline: 1.0432x; 1.0432x over previous
#include <cuda_runtime.h>
#include <cuda_bf16.h>
#include <cstdint>

// Problem constants (fixed by the reference).
#define N_ENT   50000
#define N_REL   16
#define N_BASES 8
#define H_DIM   128
#define N_EDGES 800000

// ---------------------------------------------------------------------------
// Device scratch (allocation-free rule: __device__ globals).
// ---------------------------------------------------------------------------
__device__ __nv_bfloat16 g_Wt_hi[17 * H_DIM * H_DIM];   // [r][o][i]  (N,K) K-major
__device__ __nv_bfloat16 g_Wt_lo[17 * H_DIM * H_DIM];
__device__ __nv_bfloat16 g_A_hi[(size_t)N_ENT * H_DIM];
__device__ __nv_bfloat16 g_A_lo[(size_t)N_ENT * H_DIM];
__device__ float         g_HR[(size_t)N_REL * N_ENT * H_DIM];
__device__ float         g_H1[(size_t)N_ENT * H_DIM];
__device__ int           g_cnt[N_ENT];
__device__ int           g_off[N_ENT];
__device__ int           g_cur[N_ENT];
__device__ uint32_t      g_pay[N_EDGES];   // rel*N_ENT + src, grouped by dst

// ---------------------------------------------------------------------------
// helpers
// ---------------------------------------------------------------------------
__device__ __forceinline__ uint32_t smem_u32(const void* p) {
    uint32_t a;
    asm("{ .reg .u64 t; cvta.to.shared.u64 t, %1; cvt.u32.u64 %0, t; }"
        : "=r"(a) : "l"(p));
    return a;
}

#define LDMX4(r0, r1, r2, r3, addr)                                           \
    asm volatile("ldmatrix.sync.aligned.m8n8.x4.shared.b16 {%0,%1,%2,%3}, [%4];" \
                 : "=r"(r0), "=r"(r1), "=r"(r2), "=r"(r3) : "r"(addr))

#define MMA_BF16(C, A, B)                                                     \
    asm volatile(                                                             \
        "mma.sync.aligned.m16n8k16.row.col.f32.bf16.bf16.f32 "                \
        "{%0,%1,%2,%3}, {%4,%5,%6,%7}, {%8,%9}, {%0,%1,%2,%3};"               \
        : "+f"((C)[0]), "+f"((C)[1]), "+f"((C)[2]), "+f"((C)[3])              \
        : "r"((A)[0]), "r"((A)[1]), "r"((A)[2]), "r"((A)[3]),                 \
          "r"((B)[0]), "r"((B)[1]))

#define CP_ASYNC16(dst, src)                                                  \
    asm volatile("cp.async.cg.shared.global [%0], [%1], 16;"                  \
                 :: "r"(dst), "l"(src))
#define CP_COMMIT()  asm volatile("cp.async.commit_group;" ::: "memory")
#define CP_WAIT0()   asm volatile("cp.async.wait_group 0;" ::: "memory")

// ---------------------------------------------------------------------------
// Edge binning by dst (proven).
// ---------------------------------------------------------------------------
__global__ void zero_cnt_kernel(int* __restrict__ cnt)
{
    int i = blockIdx.x * blockDim.x + threadIdx.x;
    if (i < N_ENT) cnt[i] = 0;
}

__global__ void hist_kernel(const int* __restrict__ dst,
                            int* __restrict__ cnt, int E)
{
    int e = blockIdx.x * blockDim.x + threadIdx.x;
    if (e >= E) return;
    atomicAdd(&cnt[dst[e]], 1);
}

__global__ __launch_bounds__(1024)
void scan_kernel(const int* __restrict__ cnt,
                 int* __restrict__ off, int* __restrict__ cur)
{
    __shared__ int ps[1024];
    const int t = threadIdx.x;
    const int CH = (N_ENT + 1023) / 1024;
    const int lo = t * CH;
    const int hi = min(lo + CH, N_ENT);
    int s = 0;
    for (int i = lo; i < hi; i++) s += cnt[i];
    ps[t] = s;
    __syncthreads();
    for (int d = 1; d < 1024; d <<= 1) {
        int v = (t >= d) ? ps[t - d] : 0;
        __syncthreads();
        ps[t] += v;
        __syncthreads();
    }
    int run = ps[t] - s;
    for (int i = lo; i < hi; i++) {
        off[i] = run;
        cur[i] = run;
        run += cnt[i];
    }
}

__global__ void fill_kernel(const int* __restrict__ src,
                            const int* __restrict__ dst,
                            const int* __restrict__ rel,
                            int* __restrict__ cur,
                            uint32_t* __restrict__ pay, int E)
{
    int e = blockIdx.x * blockDim.x + threadIdx.x;
    if (e >= E) return;
    int pos = atomicAdd(&cur[dst[e]], 1);
    pay[pos] = (uint32_t)(rel[e] * N_ENT + src[e]);
}

// ---------------------------------------------------------------------------
// Combine bases -> transposed bf16 hi/lo weights.
// ---------------------------------------------------------------------------
__global__ void combine_bases_kernel(const float* __restrict__ basis,
                                     const float* __restrict__ w_comp,
                                     const float* __restrict__ loop_w,
                                     __nv_bfloat16* __restrict__ Wt_hi,
                                     __nv_bfloat16* __restrict__ Wt_lo)
{
    int idx = blockIdx.x * blockDim.x + threadIdx.x;
    const int total = 17 * H_DIM * H_DIM;
    if (idx >= total) return;
    int r  = idx >> 14;
    int io = idx & 16383;          // i*128 + o
    float s;
    if (r < N_REL) {
        s = 0.f;
#pragma unroll
        for (int b = 0; b < N_BASES; b++)
            s += w_comp[r * N_BASES + b] * basis[b * (H_DIM * H_DIM) + io];
    } else {
        s = loop_w[io];
    }
    int i = io >> 7, o = io & 127;
    size_t oidx = (size_t)r * 16384 + o * 128 + i;   // [r][o][i]
    __nv_bfloat16 hi = __float2bfloat16(s);
    __nv_bfloat16 lo = __float2bfloat16(s - __bfloat162float(hi));
    Wt_hi[oidx] = hi;
    Wt_lo[oidx] = lo;
}

// ---------------------------------------------------------------------------
// Split input activations fp32 -> bf16 hi/lo (optional fused ReLU).
// ---------------------------------------------------------------------------
__global__ void split_kernel(const float* __restrict__ x,
                             __nv_bfloat16* __restrict__ hi,
                             __nv_bfloat16* __restrict__ lo,
                             int n4, int relu)
{
    int i = blockIdx.x * blockDim.x + threadIdx.x;
    if (i >= n4) return;
    float4 v = ((const float4*)x)[i];
    if (relu) {
        v.x = fmaxf(v.x, 0.f); v.y = fmaxf(v.y, 0.f);
        v.z = fmaxf(v.z, 0.f); v.w = fmaxf(v.w, 0.f);
    }
    float e[4] = {v.x, v.y, v.z, v.w};
    __nv_bfloat16 h[4], l[4];
#pragma unroll
    for (int j = 0; j < 4; j++) {
        h[j] = __float2bfloat16(e[j]);
        l[j] = __float2bfloat16(e[j] - __bfloat162float(h[j]));
    }
    ((__nv_bfloat162*)hi)[2 * i]     = __nv_bfloat162(h[0], h[1]);
    ((__nv_bfloat162*)hi)[2 * i + 1] = __nv_bfloat162(h[2], h[3]);
    ((__nv_bfloat162*)lo)[2 * i]     = __nv_bfloat162(l[0], l[1]);
    ((__nv_bfloat162*)lo)[2 * i + 1] = __nv_bfloat162(l[2], l[3]);
}

// ---------------------------------------------------------------------------
// bf16 mma.sync GEMM, CTA tile 128x128, 8 warps (4M x 2N), warp tile 32x64
// (round-9 proven shape), A resident across all 17 r's, W double-buffered
// via cp.async, 3-term bf16 split.  NEW: register-level fragment
// double-buffering — kstep k+1's 12 LDMX4 issue before kstep k's 24 MMAs,
// hiding LDSM latency under MMA issue within each warp.
// r<16 -> HR[r]; r==16 -> OUT (+bias).
// ---------------------------------------------------------------------------
#define PITCH    272                    // 256B row + 16B pad
#define SM_A_HI  0
#define SM_A_LO  34816                  // 128*272
#define SM_W0    69632                  // W stage 0: hi @+0, lo @+34816
#define W_STAGE  69632                  // bytes per stage (hi+lo)
#define GEMM_SMEM (SM_W0 + 2 * W_STAGE) // 208896

__global__ __launch_bounds__(256, 1)
void gemm_bf16_kernel(const __nv_bfloat16* __restrict__ Ahi,
                      const __nv_bfloat16* __restrict__ Alo,
                      const __nv_bfloat16* __restrict__ Wthi,
                      const __nv_bfloat16* __restrict__ Wtlo,
                      const float* __restrict__ bias,
                      float* __restrict__ HR,
                      float* __restrict__ OUT,
                      int M)
{
    extern __shared__ char smem[];
    const uint32_t sb = smem_u32(smem);
    const int tid   = threadIdx.x;
    const int wid   = tid >> 5;
    const int lane  = tid & 31;
    const int wm    = wid >> 1;              // 0..3  (32-row strips)
    const int wn    = wid & 1;               // 0..1  (64-col strips)
    const int m0    = blockIdx.x * 128;

    // ---- A tiles (hi, lo) via cp.async; OOB rows zeroed by STS ----
#pragma unroll
    for (int t = 0; t < 2; t++) {
        const __nv_bfloat16* src = t ? Alo : Ahi;
        const uint32_t base = sb + (t ? SM_A_LO : SM_A_HI);
#pragma unroll
        for (int i = 0; i < 8; i++) {
            int idx = tid + i * 256;         // 0..2047
            int row = idx >> 4;
            int c   = idx & 15;
            uint32_t dst = base + row * PITCH + c * 16;
            if (m0 + row < M)
                CP_ASYNC16(dst, src + (size_t)(m0 + row) * H_DIM + c * 8);
            else
                *(uint4*)(smem + (dst - sb)) = make_uint4(0u, 0u, 0u, 0u);
        }
    }
    // ---- prefetch W[0] into stage 0 ----
#pragma unroll
    for (int t = 0; t < 2; t++) {
        const __nv_bfloat16* src = t ? Wtlo : Wthi;
        const uint32_t base = sb + SM_W0 + t * 34816;
#pragma unroll
        for (int i = 0; i < 8; i++) {
            int idx = tid + i * 256;
            int row = idx >> 4;
            int c   = idx & 15;
            CP_ASYNC16(base + row * PITCH + c * 16,
                       src + (size_t)row * H_DIM + c * 8);
        }
    }
    CP_COMMIT();

    // ldmatrix per-lane address components
    const int q   = lane >> 3;               // 0..3
    const int r8  = lane & 7;
    const int arow_base = wm * 32 + r8 + (q & 1) * 8;     // + mt*16
    const int acol_add  = (q >> 1) * 8;                   // + k0
    const int brow_base = wn * 64 + (q >> 1) * 8 + r8;    // + p*16
    const int bcol_add  = (q & 1) * 8;                    // + k0
    const int gr0 = m0 + wm * 32 + (lane >> 2);

    // double-buffered register fragments
    uint32_t ah[2][2][4], al[2][2][4], bh[2][8][2], bl[2][8][2];

#define LOAD_FRAGS(kss, bufi)                                                 \
    do {                                                                      \
        const int _k0 = (kss) * 16;                                           \
        _Pragma("unroll")                                                     \
        for (int mt = 0; mt < 2; mt++) {                                      \
            uint32_t off = (uint32_t)((arow_base + mt * 16) * PITCH           \
                                      + (_k0 + acol_add) * 2);                \
            LDMX4(ah[bufi][mt][0], ah[bufi][mt][1],                           \
                  ah[bufi][mt][2], ah[bufi][mt][3], sb + SM_A_HI + off);      \
            LDMX4(al[bufi][mt][0], al[bufi][mt][1],                           \
                  al[bufi][mt][2], al[bufi][mt][3], sb + SM_A_LO + off);      \
        }                                                                     \
        _Pragma("unroll")                                                     \
        for (int p = 0; p < 4; p++) {                                         \
            uint32_t off = (uint32_t)((brow_base + p * 16) * PITCH            \
                                      + (_k0 + bcol_add) * 2);                \
            LDMX4(bh[bufi][2 * p][0], bh[bufi][2 * p][1],                     \
                  bh[bufi][2 * p + 1][0], bh[bufi][2 * p + 1][1], wb + off);  \
            LDMX4(bl[bufi][2 * p][0], bl[bufi][2 * p][1],                     \
                  bl[bufi][2 * p + 1][0], bl[bufi][2 * p + 1][1],             \
                  wb + 34816 + off);                                          \
        }                                                                     \
    } while (0)

    for (int r = 0; r < 17; r++) {
        CP_WAIT0();
        __syncthreads();                 // W[r] visible; other stage free

        // prefetch W[r+1] into the other stage (overlaps MMA + epilogue)
        if (r < 16) {
            const uint32_t sbase = sb + SM_W0 + ((r + 1) & 1) * W_STAGE;
#pragma unroll
            for (int t = 0; t < 2; t++) {
                const __nv_bfloat16* src =
                    (t ? Wtlo : Wthi) + (size_t)(r + 1) * 16384;
                const uint32_t base = sbase + t * 34816;
#pragma unroll
                for (int i = 0; i < 8; i++) {
                    int idx = tid + i * 256;
                    int row = idx >> 4;
                    int c   = idx & 15;
                    CP_ASYNC16(base + row * PITCH + c * 16,
                               src + (size_t)row * H_DIM + c * 8);
                }
            }
            CP_COMMIT();
        }

        const uint32_t wb = sb + SM_W0 + (r & 1) * W_STAGE;   // hi; lo @+34816

        float acc[2][8][4];
#pragma unroll
        for (int mt = 0; mt < 2; mt++)
#pragma unroll
            for (int nt = 0; nt < 8; nt++)
#pragma unroll
                for (int c = 0; c < 4; c++) acc[mt][nt][c] = 0.f;

        LOAD_FRAGS(0, 0);
#pragma unroll
        for (int ks = 0; ks < 8; ks++) {
            const int cur = ks & 1;
            if (ks < 7) LOAD_FRAGS(ks + 1, (ks + 1) & 1);
#pragma unroll
            for (int mt = 0; mt < 2; mt++)
#pragma unroll
                for (int nt = 0; nt < 8; nt++) {
                    MMA_BF16(acc[mt][nt], ah[cur][mt], bh[cur][nt]);
                    MMA_BF16(acc[mt][nt], ah[cur][mt], bl[cur][nt]);
                    MMA_BF16(acc[mt][nt], al[cur][mt], bh[cur][nt]);
                }
        }

        // ---- epilogue (registers -> global) ----
        float* base = (r < N_REL) ? (HR + (size_t)r * N_ENT * H_DIM) : OUT;
#pragma unroll
        for (int mt = 0; mt < 2; mt++) {
            int row = gr0 + mt * 16;
#pragma unroll
            for (int nt = 0; nt < 8; nt++) {
                int col = wn * 64 + nt * 8 + (lane & 3) * 2;
                float b0 = 0.f, b1 = 0.f;
                if (r == N_REL) {
                    float2 bv = *(const float2*)(bias + col);
                    b0 = bv.x; b1 = bv.y;
                }
                if (row < M)
                    *(float2*)(base + (size_t)row * H_DIM + col) =
                        make_float2(acc[mt][nt][0] + b0, acc[mt][nt][1] + b1);
                if (row + 8 < M)
                    *(float2*)(base + (size_t)(row + 8) * H_DIM + col) =
                        make_float2(acc[mt][nt][2] + b0, acc[mt][nt][3] + b1);
            }
        }
    }
#undef LOAD_FRAGS
}

// ---------------------------------------------------------------------------
// CSR-by-dst scatter, NO atomics (proven).
// ---------------------------------------------------------------------------
__global__ void scatter_csr_kernel(const float* __restrict__ HR,
                                   const int* __restrict__ off,
                                   const int* __restrict__ cnt,
                                   const uint32_t* __restrict__ pay,
                                   float* __restrict__ out)
{
    int w    = (blockIdx.x * blockDim.x + threadIdx.x) >> 5;
    int lane = threadIdx.x & 31;
    if (w >= N_ENT) return;
    int n = cnt[w];
    if (n == 0) return;
    int o = off[w];

    float4 acc = make_float4(0.f, 0.f, 0.f, 0.f);
    for (int e = 0; e < n; e++) {
        uint32_t gi = pay[o + e];
        const float4 v = *(const float4*)(HR + (size_t)gi * H_DIM + lane * 4);
        acc.x += v.x; acc.y += v.y; acc.z += v.z; acc.w += v.w;
    }
    float* op = out + (size_t)w * H_DIM + lane * 4;
    float4 c = *(const float4*)op;
    c.x += acc.x; c.y += acc.y; c.z += acc.z; c.w += acc.w;
    *(float4*)op = c;
}

// ---------------------------------------------------------------------------
// Final ReLU.
// ---------------------------------------------------------------------------
__global__ void relu_kernel(float* __restrict__ x, int n4)
{
    int i = blockIdx.x * blockDim.x + threadIdx.x;
    if (i >= n4) return;
    float4 v = ((float4*)x)[i];
    v.x = fmaxf(v.x, 0.f); v.y = fmaxf(v.y, 0.f);
    v.z = fmaxf(v.z, 0.f); v.w = fmaxf(v.w, 0.f);
    ((float4*)x)[i] = v;
}

// ---------------------------------------------------------------------------
// Launch. Order keeps gemm (layer 1) in the ncu-profiled slot (#4).
// ---------------------------------------------------------------------------
extern "C" void kernel_launch(void* const* d_in, const int* in_sizes, int n_in,
                              void* d_out, int out_size)
{
    const float* entity_emb = (const float*)d_in[0];
    const float* basis1     = (const float*)d_in[1];
    const float* w_comp1    = (const float*)d_in[2];
    const float* loop_w1    = (const float*)d_in[3];
    const float* bias1      = (const float*)d_in[4];
    const float* basis2     = (const float*)d_in[5];
    const float* w_comp2    = (const float*)d_in[6];
    const float* loop_w2    = (const float*)d_in[7];
    const float* bias2      = (const float*)d_in[8];
    const int*   src        = (const int*)d_in[9];
    const int*   dst        = (const int*)d_in[10];
    const int*   rel        = (const int*)d_in[11];
    float*       out        = (float*)d_out;

    const int E = in_sizes[9];

    __nv_bfloat16 *dWth, *dWtl, *dAh, *dAl;
    float *dHR, *dH1;
    int *dcnt, *doff, *dcur;
    uint32_t *dpay;
    cudaGetSymbolAddress((void**)&dWth, g_Wt_hi);
    cudaGetSymbolAddress((void**)&dWtl, g_Wt_lo);
    cudaGetSymbolAddress((void**)&dAh,  g_A_hi);
    cudaGetSymbolAddress((void**)&dAl,  g_A_lo);
    cudaGetSymbolAddress((void**)&dHR,  g_HR);
    cudaGetSymbolAddress((void**)&dH1,  g_H1);
    cudaGetSymbolAddress((void**)&dcnt, g_cnt);
    cudaGetSymbolAddress((void**)&doff, g_off);
    cudaGetSymbolAddress((void**)&dcur, g_cur);
    cudaGetSymbolAddress((void**)&dpay, g_pay);

    cudaFuncSetAttribute(gemm_bf16_kernel,
                         cudaFuncAttributeMaxDynamicSharedMemorySize, GEMM_SMEM);

    const int cb_blocks = (17 * H_DIM * H_DIM + 255) / 256;
    const int n4        = N_ENT * H_DIM / 4;
    const int sp_blocks = (n4 + 255) / 256;
    const int eg_blocks = (E + 255) / 256;
    const int zc_blocks = (N_ENT + 255) / 256;
    const int gemm_grid = (N_ENT + 127) / 128;       // 391
    const int csr_blocks = (N_ENT * 32 + 255) / 256;

    // #1..#4 (gemm layer-1 lands in the profiled slot)
    combine_bases_kernel<<<cb_blocks, 256>>>(basis1, w_comp1, loop_w1, dWth, dWtl);
    split_kernel<<<sp_blocks, 256>>>(entity_emb, dAh, dAl, n4, 0);
    zero_cnt_kernel<<<zc_blocks, 256>>>(dcnt);
    gemm_bf16_kernel<<<gemm_grid, 256, GEMM_SMEM>>>(dAh, dAl, dWth, dWtl, bias1,
                                                    dHR, dH1, N_ENT);
    // binning (needed before scatter)
    hist_kernel<<<eg_blocks, 256>>>(dst, dcnt, E);
    scan_kernel<<<1, 1024>>>(dcnt, doff, dcur);
    fill_kernel<<<eg_blocks, 256>>>(src, dst, rel, dcur, dpay, E);
    scatter_csr_kernel<<<csr_blocks, 256>>>(dHR, doff, dcnt, dpay, dH1);

    // ---------------- Layer 2 ----------------
    combine_bases_kernel<<<cb_blocks, 256>>>(basis2, w_comp2, loop_w2, dWth, dWtl);
    split_kernel<<<sp_blocks, 256>>>(dH1, dAh, dAl, n4, 1);   // fused ReLU
    gemm_bf16_kernel<<<gemm_grid, 256, GEMM_SMEM>>>(dAh, dAl, dWth, dWtl, bias2,
                                                    dHR, out, N_ENT);
    scatter_csr_kernel<<<csr_blocks, 256>>>(dHR, doff, dcnt, dpay, out);
    relu_kernel<<<sp_blocks, 256>>>(out, n4);
}

// round 12
// speedup vs baseline: 1.3821x; 1.3249x over previous
#include <cuda_runtime.h>
#include <cuda_bf16.h>
#include <cstdint>

// Problem constants (fixed by the reference).
#define N_ENT   50000
#define N_REL   16
#define N_BASES 8
#define H_DIM   128
#define N_EDGES 800000

// ---------------------------------------------------------------------------
// Device scratch (allocation-free rule: __device__ globals).
// g_Wt  : 9 planes [g][o][i] bf16 hi/lo  (g<8: basis_b transposed; g=8: loop_w)
// g_comp: 8 planes [b][n][128] bf16 hi/lo (relation-compressed aggregates)
// ---------------------------------------------------------------------------
__device__ __nv_bfloat16 g_Wt_hi[9 * H_DIM * H_DIM];
__device__ __nv_bfloat16 g_Wt_lo[9 * H_DIM * H_DIM];
__device__ __nv_bfloat16 g_A_hi[(size_t)N_ENT * H_DIM];
__device__ __nv_bfloat16 g_A_lo[(size_t)N_ENT * H_DIM];
__device__ __nv_bfloat16 g_comp_hi[(size_t)N_BASES * N_ENT * H_DIM];
__device__ __nv_bfloat16 g_comp_lo[(size_t)N_BASES * N_ENT * H_DIM];
__device__ float         g_H1[(size_t)N_ENT * H_DIM];
__device__ int           g_cnt[N_ENT];
__device__ int           g_off[N_ENT + 1];
__device__ int           g_cur[N_ENT];
__device__ uint32_t      g_pay[N_EDGES];   // (rel<<16) | src, grouped by dst

// ---------------------------------------------------------------------------
// helpers
// ---------------------------------------------------------------------------
__device__ __forceinline__ uint32_t smem_u32(const void* p) {
    uint32_t a;
    asm("{ .reg .u64 t; cvta.to.shared.u64 t, %1; cvt.u32.u64 %0, t; }"
        : "=r"(a) : "l"(p));
    return a;
}

#define LDMX4(r0, r1, r2, r3, addr)                                           \
    asm volatile("ldmatrix.sync.aligned.m8n8.x4.shared.b16 {%0,%1,%2,%3}, [%4];" \
                 : "=r"(r0), "=r"(r1), "=r"(r2), "=r"(r3) : "r"(addr))

#define MMA_BF16(C, A, B)                                                     \
    asm volatile(                                                             \
        "mma.sync.aligned.m16n8k16.row.col.f32.bf16.bf16.f32 "                \
        "{%0,%1,%2,%3}, {%4,%5,%6,%7}, {%8,%9}, {%0,%1,%2,%3};"               \
        : "+f"((C)[0]), "+f"((C)[1]), "+f"((C)[2]), "+f"((C)[3])              \
        : "r"((A)[0]), "r"((A)[1]), "r"((A)[2]), "r"((A)[3]),                 \
          "r"((B)[0]), "r"((B)[1]))

#define CP_ASYNC16(dst, src)                                                  \
    asm volatile("cp.async.cg.shared.global [%0], [%1], 16;"                  \
                 :: "r"(dst), "l"(src))
#define CP_COMMIT()  asm volatile("cp.async.commit_group;" ::: "memory")
#define CP_WAIT0()   asm volatile("cp.async.wait_group 0;" ::: "memory")

__device__ __forceinline__ uint32_t bf2x(float a, float b) {
    __nv_bfloat162 t(__float2bfloat16(a), __float2bfloat16(b));
    return *(uint32_t*)&t;
}

// ---------------------------------------------------------------------------
// Edge binning by dst. hist expects cnt==0 (zeroed by scan of previous call;
// static-initialized zero on the first call). scan zeroes cnt after reading.
// ---------------------------------------------------------------------------
__global__ void hist_kernel(const int* __restrict__ dst,
                            int* __restrict__ cnt, int E)
{
    int e = blockIdx.x * blockDim.x + threadIdx.x;
    if (e >= E) return;
    atomicAdd(&cnt[dst[e]], 1);
}

__global__ __launch_bounds__(1024)
void scan_kernel(int* __restrict__ cnt,
                 int* __restrict__ off, int* __restrict__ cur)
{
    __shared__ int ps[1024];
    const int t = threadIdx.x;
    const int CH = (N_ENT + 1023) / 1024;
    const int lo = t * CH;
    const int hi = min(lo + CH, N_ENT);
    int s = 0;
    for (int i = lo; i < hi; i++) s += cnt[i];
    ps[t] = s;
    __syncthreads();
    for (int d = 1; d < 1024; d <<= 1) {
        int v = (t >= d) ? ps[t - d] : 0;
        __syncthreads();
        ps[t] += v;
        __syncthreads();
    }
    int run = ps[t] - s;
    for (int i = lo; i < hi; i++) {
        off[i] = run;
        cur[i] = run;
        run += cnt[i];
        cnt[i] = 0;                       // re-zero for next call's hist
    }
    if (t == 1023) off[N_ENT] = run;      // grand total
}

__global__ void fill_kernel(const int* __restrict__ src,
                            const int* __restrict__ dst,
                            const int* __restrict__ rel,
                            int* __restrict__ cur,
                            uint32_t* __restrict__ pay, int E)
{
    int e = blockIdx.x * blockDim.x + threadIdx.x;
    if (e >= E) return;
    int pos = atomicAdd(&cur[dst[e]], 1);
    pay[pos] = ((uint32_t)rel[e] << 16) | (uint32_t)src[e];
}

// ---------------------------------------------------------------------------
// Aggregate: warp per dst node. compact[n,b] = sum_edges w_comp[rel,b]*h[src]
// (fp32 accumulation, no atomics), emitted as bf16 hi/lo planes [b][n][128].
// Nodes with no edges write zeros (GEMM reads every row).
// ---------------------------------------------------------------------------
__global__ __launch_bounds__(256)
void agg_kernel(const float* __restrict__ h,
                const uint32_t* __restrict__ pay,
                const int* __restrict__ off,
                const float* __restrict__ w_comp,
                __nv_bfloat16* __restrict__ comp_hi,
                __nv_bfloat16* __restrict__ comp_lo,
                int relu)
{
    __shared__ float wc[N_REL][N_BASES];
    const int tid = threadIdx.x;
    if (tid < N_REL * N_BASES) wc[tid >> 3][tid & 7] = w_comp[tid];
    __syncthreads();

    const int w    = (blockIdx.x * blockDim.x + tid) >> 5;
    const int lane = tid & 31;
    if (w >= N_ENT) return;

    const int o0 = off[w];
    const int n  = off[w + 1] - o0;

    float cb[N_BASES][4];
#pragma unroll
    for (int b = 0; b < N_BASES; b++)
#pragma unroll
        for (int c = 0; c < 4; c++) cb[b][c] = 0.f;

    for (int e = 0; e < n; e++) {
        uint32_t p = pay[o0 + e];
        int r = (int)(p >> 16);
        int s = (int)(p & 0xFFFFu);
        float4 v = *(const float4*)(h + (size_t)s * H_DIM + lane * 4);
        if (relu) {
            v.x = fmaxf(v.x, 0.f); v.y = fmaxf(v.y, 0.f);
            v.z = fmaxf(v.z, 0.f); v.w = fmaxf(v.w, 0.f);
        }
#pragma unroll
        for (int b = 0; b < N_BASES; b++) {
            float wcb = wc[r][b];
            cb[b][0] = fmaf(wcb, v.x, cb[b][0]);
            cb[b][1] = fmaf(wcb, v.y, cb[b][1]);
            cb[b][2] = fmaf(wcb, v.z, cb[b][2]);
            cb[b][3] = fmaf(wcb, v.w, cb[b][3]);
        }
    }

#pragma unroll
    for (int b = 0; b < N_BASES; b++) {
        size_t base = ((size_t)b * N_ENT + w) * H_DIM + lane * 4;
        float hi[4], lo[4];
#pragma unroll
        for (int c = 0; c < 4; c++) {
            hi[c] = __bfloat162float(__float2bfloat16(cb[b][c]));
            lo[c] = cb[b][c] - hi[c];
        }
        uint2 uh, ul;
        uh.x = bf2x(hi[0], hi[1]); uh.y = bf2x(hi[2], hi[3]);
        ul.x = bf2x(lo[0], lo[1]); ul.y = bf2x(lo[2], lo[3]);
        *(uint2*)(comp_hi + base) = uh;
        *(uint2*)(comp_lo + base) = ul;
    }
}

// ---------------------------------------------------------------------------
// Prep W planes: g<8 -> basis[g] transposed [o][i]; g==8 -> loop_w transposed.
// ---------------------------------------------------------------------------
__global__ void prep_w_kernel(const float* __restrict__ basis,
                              const float* __restrict__ loop_w,
                              __nv_bfloat16* __restrict__ Wt_hi,
                              __nv_bfloat16* __restrict__ Wt_lo)
{
    int idx = blockIdx.x * blockDim.x + threadIdx.x;
    const int total = 9 * H_DIM * H_DIM;
    if (idx >= total) return;
    int g  = idx >> 14;
    int io = idx & 16383;                  // i*128 + o
    float s = (g < 8) ? basis[g * 16384 + io] : loop_w[io];
    int i = io >> 7, o = io & 127;
    size_t oidx = (size_t)g * 16384 + o * 128 + i;   // [g][o][i]
    __nv_bfloat16 hi = __float2bfloat16(s);
    __nv_bfloat16 lo = __float2bfloat16(s - __bfloat162float(hi));
    Wt_hi[oidx] = hi;
    Wt_lo[oidx] = lo;
}

// ---------------------------------------------------------------------------
// Split input activations fp32 -> bf16 hi/lo (optional fused ReLU).
// ---------------------------------------------------------------------------
__global__ void split_kernel(const float* __restrict__ x,
                             __nv_bfloat16* __restrict__ hi,
                             __nv_bfloat16* __restrict__ lo,
                             int n4, int relu)
{
    int i = blockIdx.x * blockDim.x + threadIdx.x;
    if (i >= n4) return;
    float4 v = ((const float4*)x)[i];
    if (relu) {
        v.x = fmaxf(v.x, 0.f); v.y = fmaxf(v.y, 0.f);
        v.z = fmaxf(v.z, 0.f); v.w = fmaxf(v.w, 0.f);
    }
    float e[4] = {v.x, v.y, v.z, v.w};
    __nv_bfloat16 h[4], l[4];
#pragma unroll
    for (int j = 0; j < 4; j++) {
        h[j] = __float2bfloat16(e[j]);
        l[j] = __float2bfloat16(e[j] - __bfloat162float(h[j]));
    }
    ((__nv_bfloat162*)hi)[2 * i]     = __nv_bfloat162(h[0], h[1]);
    ((__nv_bfloat162*)hi)[2 * i + 1] = __nv_bfloat162(h[2], h[3]);
    ((__nv_bfloat162*)lo)[2 * i]     = __nv_bfloat162(l[0], l[1]);
    ((__nv_bfloat162*)lo)[2 * i + 1] = __nv_bfloat162(l[2], l[3]);
}

// ---------------------------------------------------------------------------
// Single K=1152 GEMM: OUT = [compact_0..7 | h] @ [[basis_0..7];[loop]] + bias.
// CTA tile 128x128, 8 warps (4M x 2N), warp tile 32x64 (R9 proven shape),
// 3-term bf16 split, fp32 acc held in registers across the whole K.
// Both A and W staged via cp.async, double-buffered (stage = A+W, 72KB).
// ---------------------------------------------------------------------------
#define PITCH9   144                    // 128B row + 16B pad
#define ST_A_HI  0
#define ST_A_LO  18432                  // 128*144
#define ST_W_HI  36864
#define ST_W_LO  55296
#define STAGE_SZ 73728
#define GEMM_SMEM (2 * STAGE_SZ)        // 147456

__global__ __launch_bounds__(256, 1)
void gemm9_kernel(const __nv_bfloat16* __restrict__ comp_hi,
                  const __nv_bfloat16* __restrict__ comp_lo,
                  const __nv_bfloat16* __restrict__ Ahi,
                  const __nv_bfloat16* __restrict__ Alo,
                  const __nv_bfloat16* __restrict__ Wthi,
                  const __nv_bfloat16* __restrict__ Wtlo,
                  const float* __restrict__ bias,
                  float* __restrict__ OUT,
                  int M)
{
    extern __shared__ char smem[];
    const uint32_t sb = smem_u32(smem);
    const int tid   = threadIdx.x;
    const int wid   = tid >> 5;
    const int lane  = tid & 31;
    const int wm    = wid >> 1;              // 0..3  (32-row strips)
    const int wn    = wid & 1;               // 0..1  (64-col strips)
    const int m0    = blockIdx.x * 128;

    // ldmatrix per-lane address components
    const int q   = lane >> 3;               // 0..3
    const int r8  = lane & 7;
    const int arow_base = wm * 32 + r8 + (q & 1) * 8;
    const int acol_add  = (q >> 1) * 8;
    const int brow_base = wn * 64 + (q >> 1) * 8 + r8;
    const int bcol_add  = (q & 1) * 8;
    const int gr0 = m0 + wm * 32 + (lane >> 2);

#define PREFETCH(t)                                                           \
    do {                                                                      \
        const int _g = (t) >> 1, _hf = (t) & 1;                               \
        const __nv_bfloat16* _ah = (_g < 8)                                   \
            ? comp_hi + (size_t)_g * N_ENT * H_DIM : Ahi;                     \
        const __nv_bfloat16* _al = (_g < 8)                                   \
            ? comp_lo + (size_t)_g * N_ENT * H_DIM : Alo;                     \
        const __nv_bfloat16* _wh = Wthi + _g * 16384;                         \
        const __nv_bfloat16* _wl = Wtlo + _g * 16384;                         \
        const uint32_t _st = sb + ((t) & 1) * STAGE_SZ;                       \
        _Pragma("unroll")                                                     \
        for (int _i = 0; _i < 4; _i++) {                                      \
            int _idx = tid + _i * 256;      /* 0..1023 */                     \
            int _row = _idx >> 3;           /* 0..127 */                      \
            int _c8  = (_idx & 7) * 8;      /* bf16 col within 64 */          \
            uint32_t _sa = _st + _row * PITCH9 + _c8 * 2;                     \
            if (m0 + _row < M) {                                              \
                CP_ASYNC16(_sa + ST_A_HI,                                     \
                    _ah + (size_t)(m0 + _row) * H_DIM + _hf * 64 + _c8);      \
                CP_ASYNC16(_sa + ST_A_LO,                                     \
                    _al + (size_t)(m0 + _row) * H_DIM + _hf * 64 + _c8);      \
            } else {                                                          \
                *(uint4*)(smem + (_sa + ST_A_HI - sb)) = make_uint4(0,0,0,0); \
                *(uint4*)(smem + (_sa + ST_A_LO - sb)) = make_uint4(0,0,0,0); \
            }                                                                 \
            CP_ASYNC16(_sa + ST_W_HI,                                         \
                _wh + (size_t)_row * H_DIM + _hf * 64 + _c8);                 \
            CP_ASYNC16(_sa + ST_W_LO,                                         \
                _wl + (size_t)_row * H_DIM + _hf * 64 + _c8);                 \
        }                                                                     \
    } while (0)

    float acc[2][8][4];
#pragma unroll
    for (int mt = 0; mt < 2; mt++)
#pragma unroll
        for (int nt = 0; nt < 8; nt++)
#pragma unroll
            for (int c = 0; c < 4; c++) acc[mt][nt][c] = 0.f;

    PREFETCH(0);
    CP_COMMIT();

    for (int t = 0; t < 18; t++) {
        CP_WAIT0();
        __syncthreads();                 // stage t ready; stage t^1 free

        if (t < 17) {
            PREFETCH(t + 1);
            CP_COMMIT();
        }

        const uint32_t st = sb + (t & 1) * STAGE_SZ;

#pragma unroll
        for (int ks = 0; ks < 4; ks++) {
            const int k0 = ks * 16;
            uint32_t ah[2][4], al[2][4], bh[8][2], bl[8][2];
#pragma unroll
            for (int mt = 0; mt < 2; mt++) {
                uint32_t off = (uint32_t)((arow_base + mt * 16) * PITCH9
                                          + (k0 + acol_add) * 2);
                LDMX4(ah[mt][0], ah[mt][1], ah[mt][2], ah[mt][3],
                      st + ST_A_HI + off);
                LDMX4(al[mt][0], al[mt][1], al[mt][2], al[mt][3],
                      st + ST_A_LO + off);
            }
#pragma unroll
            for (int p = 0; p < 4; p++) {
                uint32_t off = (uint32_t)((brow_base + p * 16) * PITCH9
                                          + (k0 + bcol_add) * 2);
                LDMX4(bh[2 * p][0], bh[2 * p][1], bh[2 * p + 1][0],
                      bh[2 * p + 1][1], st + ST_W_HI + off);
                LDMX4(bl[2 * p][0], bl[2 * p][1], bl[2 * p + 1][0],
                      bl[2 * p + 1][1], st + ST_W_LO + off);
            }
#pragma unroll
            for (int mt = 0; mt < 2; mt++)
#pragma unroll
                for (int nt = 0; nt < 8; nt++) {
                    MMA_BF16(acc[mt][nt], ah[mt], bh[nt]);
                    MMA_BF16(acc[mt][nt], ah[mt], bl[nt]);
                    MMA_BF16(acc[mt][nt], al[mt], bh[nt]);
                }
        }
        __syncthreads();                 // all warps done with stage t
    }

    // ---- epilogue: OUT = acc + bias ----
#pragma unroll
    for (int mt = 0; mt < 2; mt++) {
        int row = gr0 + mt * 16;
#pragma unroll
        for (int nt = 0; nt < 8; nt++) {
            int col = wn * 64 + nt * 8 + (lane & 3) * 2;
            float2 bv = *(const float2*)(bias + col);
            if (row < M)
                *(float2*)(OUT + (size_t)row * H_DIM + col) =
                    make_float2(acc[mt][nt][0] + bv.x, acc[mt][nt][1] + bv.y);
            if (row + 8 < M)
                *(float2*)(OUT + (size_t)(row + 8) * H_DIM + col) =
                    make_float2(acc[mt][nt][2] + bv.x, acc[mt][nt][3] + bv.y);
        }
    }
#undef PREFETCH
}

// ---------------------------------------------------------------------------
// Final ReLU.
// ---------------------------------------------------------------------------
__global__ void relu_kernel(float* __restrict__ x, int n4)
{
    int i = blockIdx.x * blockDim.x + threadIdx.x;
    if (i >= n4) return;
    float4 v = ((float4*)x)[i];
    v.x = fmaxf(v.x, 0.f); v.y = fmaxf(v.y, 0.f);
    v.z = fmaxf(v.z, 0.f); v.w = fmaxf(v.w, 0.f);
    ((float4*)x)[i] = v;
}

// ---------------------------------------------------------------------------
// Launch. agg1 is the 4th launch -> ncu-profiled.
// ---------------------------------------------------------------------------
extern "C" void kernel_launch(void* const* d_in, const int* in_sizes, int n_in,
                              void* d_out, int out_size)
{
    const float* entity_emb = (const float*)d_in[0];
    const float* basis1     = (const float*)d_in[1];
    const float* w_comp1    = (const float*)d_in[2];
    const float* loop_w1    = (const float*)d_in[3];
    const float* bias1      = (const float*)d_in[4];
    const float* basis2     = (const float*)d_in[5];
    const float* w_comp2    = (const float*)d_in[6];
    const float* loop_w2    = (const float*)d_in[7];
    const float* bias2      = (const float*)d_in[8];
    const int*   src        = (const int*)d_in[9];
    const int*   dst        = (const int*)d_in[10];
    const int*   rel        = (const int*)d_in[11];
    float*       out        = (float*)d_out;

    const int E = in_sizes[9];

    __nv_bfloat16 *dWth, *dWtl, *dAh, *dAl, *dCh, *dCl;
    float *dH1;
    int *dcnt, *doff, *dcur;
    uint32_t *dpay;
    cudaGetSymbolAddress((void**)&dWth, g_Wt_hi);
    cudaGetSymbolAddress((void**)&dWtl, g_Wt_lo);
    cudaGetSymbolAddress((void**)&dAh,  g_A_hi);
    cudaGetSymbolAddress((void**)&dAl,  g_A_lo);
    cudaGetSymbolAddress((void**)&dCh,  g_comp_hi);
    cudaGetSymbolAddress((void**)&dCl,  g_comp_lo);
    cudaGetSymbolAddress((void**)&dH1,  g_H1);
    cudaGetSymbolAddress((void**)&dcnt, g_cnt);
    cudaGetSymbolAddress((void**)&doff, g_off);
    cudaGetSymbolAddress((void**)&dcur, g_cur);
    cudaGetSymbolAddress((void**)&dpay, g_pay);

    cudaFuncSetAttribute(gemm9_kernel,
                         cudaFuncAttributeMaxDynamicSharedMemorySize, GEMM_SMEM);

    const int pw_blocks = (9 * H_DIM * H_DIM + 255) / 256;
    const int n4        = N_ENT * H_DIM / 4;
    const int sp_blocks = (n4 + 255) / 256;
    const int eg_blocks = (E + 255) / 256;
    const int gemm_grid = (N_ENT + 127) / 128;       // 391
    const int agg_blocks = (N_ENT * 32 + 255) / 256;

    // ---------------- binning (cnt pre-zeroed; scan re-zeroes) ----------------
    hist_kernel<<<eg_blocks, 256>>>(dst, dcnt, E);
    scan_kernel<<<1, 1024>>>(dcnt, doff, dcur);
    fill_kernel<<<eg_blocks, 256>>>(src, dst, rel, dcur, dpay, E);

    // ---------------- Layer 1 ----------------
    agg_kernel<<<agg_blocks, 256>>>(entity_emb, dpay, doff, w_comp1,
                                    dCh, dCl, 0);              // profiled (#4)
    prep_w_kernel<<<pw_blocks, 256>>>(basis1, loop_w1, dWth, dWtl);
    split_kernel<<<sp_blocks, 256>>>(entity_emb, dAh, dAl, n4, 0);
    gemm9_kernel<<<gemm_grid, 256, GEMM_SMEM>>>(dCh, dCl, dAh, dAl,
                                                dWth, dWtl, bias1, dH1, N_ENT);

    // ---------------- Layer 2 ----------------
    agg_kernel<<<agg_blocks, 256>>>(dH1, dpay, doff, w_comp2,
                                    dCh, dCl, 1);              // fused ReLU
    prep_w_kernel<<<pw_blocks, 256>>>(basis2, loop_w2, dWth, dWtl);
    split_kernel<<<sp_blocks, 256>>>(dH1, dAh, dAl, n4, 1);    // fused ReLU
    gemm9_kernel<<<gemm_grid, 256, GEMM_SMEM>>>(dCh, dCl, dAh, dAl,
                                                dWth, dWtl, bias2, out, N_ENT);
    relu_kernel<<<sp_blocks, 256>>>(out, n4);
}